// round 13
// baseline (speedup 1.0000x reference)
#include <cuda_runtime.h>
#include <cuda_bf16.h>
#include <cstdint>
#include <math.h>

typedef unsigned int u32;

#define VV    32768
#define NSEQ  1024
#define LSEQ  32
#define CD    128
#define DIc   256

typedef __nv_bfloat16 bf16;

// ---------------- scratch (device globals: allocation-free) ----------------
__device__ __align__(16) bf16  g_xn  [(size_t)VV * CD];
__device__ __align__(16) bf16  g_z   [3ull * VV * DIc];
__device__ __align__(16) bf16  g_xc  [3ull * VV * DIc];
__device__ __align__(16) float g_dbl [3ull * VV * 40];
__device__ __align__(16) bf16  g_ymid[3ull * VV * DIc];
__device__ __align__(16) bf16  g_yb  [(size_t)VV * 384];   // reused as [3][VV][128] per-branch proj contributions
__device__ __align__(16) bf16  g_f   [(size_t)VV * CD];

__device__ __align__(16) bf16 g_w_in [3 * 512 * 128];
__device__ __align__(16) bf16 g_w_xp [3 * 40 * 256];
__device__ __align__(16) bf16 g_w_c  [3 * 128 * 256];      // combined Wf_r @ Wout_r
__device__ __align__(16) bf16 g_w_p  [128 * 128];

__device__ __forceinline__ int vox_of(int r, int m) {
    int n = m >> 5, t = m & 31;
    if (r == 0) return (t << 10) + n;
    if (r == 1) return ((n >> 5) << 10) + (t << 5) + (n & 31);
    return (n << 5) + t;
}

// ---------------- weight convert fp32 -> bf16 ----------------
__global__ __launch_bounds__(256) void cvt_kernel(
    const float* __restrict__ in_w, const float* __restrict__ xp_w,
    const float* __restrict__ pw)
{
    const int i = blockIdx.x * 256 + threadIdx.x;
    if (i < 3 * 512 * 128) g_w_in[i] = __float2bfloat16(in_w[i]);
    if (i < 3 * 40 * 256)  g_w_xp[i] = __float2bfloat16(xp_w[i]);
    if (i < 128 * 128)     g_w_p[i]  = __float2bfloat16(pw[i]);
}

// ---------------- combined weight: W'_r = Wf[:, r*128:+128] @ Wout_r  (fp32) ----------------
__global__ __launch_bounds__(256) void wcomb_kernel(
    const float* __restrict__ fw, const float* __restrict__ out_w)
{
    const int r = blockIdx.y, o = blockIdx.x, k = threadIdx.x;
    float s = 0.f;
    #pragma unroll 8
    for (int j = 0; j < 128; j++)
        s = fmaf(fw[o * 384 + r * 128 + j], out_w[((size_t)r * 128 + j) * 256 + k], s);
    g_w_c[((size_t)r * 128 + o) * 256 + k] = __float2bfloat16(s);
}

// ---------------- LayerNorm ----------------
__global__ __launch_bounds__(256) void ln_kernel(
    const float* __restrict__ x, const float* __restrict__ g, const float* __restrict__ b)
{
    __shared__ float sm[128][33];
    __shared__ float smu[32], srs[32];
    const int v0 = blockIdx.x * 32;
    const int tid = threadIdx.x;

    #pragma unroll
    for (int it = 0; it < 16; it++) {
        int e = it * 256 + tid;
        int c = e >> 5, vi = e & 31;
        sm[c][vi] = x[(size_t)c * VV + v0 + vi];
    }
    __syncthreads();
    if (tid < 32) {
        float s = 0.f, s2 = 0.f;
        #pragma unroll 8
        for (int c = 0; c < 128; c++) { float v = sm[c][tid]; s += v; s2 += v * v; }
        float m = s * (1.f / 128.f);
        float var = s2 * (1.f / 128.f) - m * m;
        smu[tid] = m;
        srs[tid] = rsqrtf(var + 1e-5f);
    }
    __syncthreads();
    #pragma unroll
    for (int it = 0; it < 16; it++) {
        int e = it * 256 + tid;
        int c = e & 127, vi = e >> 7;
        float v = (sm[c][vi] - smu[vi]) * srs[vi] * g[c] + b[c];
        g_xn[(size_t)(v0 + vi) * 128 + c] = __float2bfloat16(v);
    }
}

// ---------------- tensor-core / async-copy helpers ----------------
__device__ __forceinline__ void ldsm4(u32* r, const void* p) {
    u32 addr = (u32)__cvta_generic_to_shared(p);
    asm volatile("ldmatrix.sync.aligned.m8n8.x4.shared.b16 {%0,%1,%2,%3}, [%4];"
        : "=r"(r[0]), "=r"(r[1]), "=r"(r[2]), "=r"(r[3]) : "r"(addr));
}
__device__ __forceinline__ void mma16816(float* c, const u32* a, u32 b0, u32 b1) {
    asm volatile("mma.sync.aligned.m16n8k16.row.col.f32.bf16.bf16.f32 "
        "{%0,%1,%2,%3}, {%4,%5,%6,%7}, {%8,%9}, {%0,%1,%2,%3};"
        : "+f"(c[0]), "+f"(c[1]), "+f"(c[2]), "+f"(c[3])
        : "r"(a[0]), "r"(a[1]), "r"(a[2]), "r"(a[3]), "r"(b0), "r"(b1));
}
__device__ __forceinline__ void cpa16(void* dst, const void* src, bool pred) {
    u32 d = (u32)__cvta_generic_to_shared(dst);
    int sz = pred ? 16 : 0;
    asm volatile("cp.async.ca.shared.global [%0], [%1], 16, %2;" :: "r"(d), "l"(src), "r"(sz));
}
__device__ __forceinline__ void cpa_commit() { asm volatile("cp.async.commit_group;"); }
template <int N> __device__ __forceinline__ void cpa_wait() {
    asm volatile("cp.async.wait_group %0;" :: "n"(N));
}
__device__ __forceinline__ float siluf(float s) { return s / (1.f + __expf(-s)); }

// ======== 128x128-tile GEMM (MODEs 1,2), 2-stage pipeline; per-branch r ========
// MODE 1: in_proj  A=g_xn gathered (K=128), N=512 -> conv+silu -> g_xc / silu -> g_z
// MODE 2: combined out_proj+fusion: A=g_ymid[r] (K=256), B=g_w_c[r] (128x256)
//         -> scatter per-branch contribution to g_yb[r][vox][128]
template <int MODE>
__global__ __launch_bounds__(256) void bgemm128_kernel(
    int r, const float* __restrict__ conv_w, const float* __restrict__ conv_b)
{
    constexpr int Kc = (MODE == 1) ? 128 : 256;
    constexpr int NSTAGE = Kc / 32;

    __shared__ __align__(16) char raw[40960];
    bf16* As = (bf16*)raw;                 // [2][128][40]
    bf16* Bs = As + 2 * 128 * 40;          // [2][128][40]

    const int m0  = blockIdx.y * 128;
    const int j0  = blockIdx.x * 128;
    const int tid = threadIdx.x;
    const int lane = tid & 31, warp = tid >> 5;
    const int wm = (warp & 3) * 32, wn = (warp >> 2) * 64;

    const bf16* Bbase = (MODE == 1) ? (g_w_in + (size_t)r * 512 * 128)
                                    : (g_w_c  + (size_t)r * 128 * 256);

    const int lrow = tid >> 2;
    const int lk8  = (tid & 3) << 3;

    const bf16 *arow0, *arow1;
    if (MODE == 1) {
        arow0 = g_xn + (size_t)vox_of(r, m0 + lrow) * 128;
        arow1 = g_xn + (size_t)vox_of(r, m0 + lrow + 64) * 128;
    } else {
        arow0 = g_ymid + (size_t)r * VV * 256 + (size_t)(m0 + lrow) * 256;
        arow1 = g_ymid + (size_t)r * VV * 256 + (size_t)(m0 + lrow + 64) * 256;
    }
    const bf16* brow0 = Bbase + (size_t)(j0 + lrow) * Kc;
    const bf16* brow1 = Bbase + (size_t)(j0 + lrow + 64) * Kc;

    float acc[2][8][4];
    #pragma unroll
    for (int f = 0; f < 2; f++)
        #pragma unroll
        for (int n = 0; n < 8; n++)
            #pragma unroll
            for (int i = 0; i < 4; i++) acc[f][n][i] = 0.f;

    const int srow = lane & 15;
    const int scol = (lane >> 4) << 3;

    cpa16(As + (lrow      ) * 40 + lk8, arow0 + lk8, true);
    cpa16(As + (lrow + 64 ) * 40 + lk8, arow1 + lk8, true);
    cpa16(Bs + (lrow      ) * 40 + lk8, brow0 + lk8, true);
    cpa16(Bs + (lrow + 64 ) * 40 + lk8, brow1 + lk8, true);
    cpa_commit();

    int sb = 0;
    #pragma unroll
    for (int st = 0; st < NSTAGE; st++) {
        const int kn = (st + 1) * 32;
        if (kn < Kc) {
            bf16* Ad = As + (sb ^ 1) * 128 * 40;
            bf16* Bd = Bs + (sb ^ 1) * 128 * 40;
            cpa16(Ad + (lrow     ) * 40 + lk8, arow0 + kn + lk8, true);
            cpa16(Ad + (lrow + 64) * 40 + lk8, arow1 + kn + lk8, true);
            cpa16(Bd + (lrow     ) * 40 + lk8, brow0 + kn + lk8, true);
            cpa16(Bd + (lrow + 64) * 40 + lk8, brow1 + kn + lk8, true);
        }
        cpa_commit();
        cpa_wait<1>();
        __syncthreads();
        const bf16* Ac = As + sb * 128 * 40;
        const bf16* Bc = Bs + sb * 128 * 40;
        #pragma unroll
        for (int kk = 0; kk < 32; kk += 16) {
            u32 a[2][4], b[4][4];
            ldsm4(a[0], Ac + (wm +      srow) * 40 + kk + scol);
            ldsm4(a[1], Ac + (wm + 16 + srow) * 40 + kk + scol);
            ldsm4(b[0], Bc + (wn +      srow) * 40 + kk + scol);
            ldsm4(b[1], Bc + (wn + 16 + srow) * 40 + kk + scol);
            ldsm4(b[2], Bc + (wn + 32 + srow) * 40 + kk + scol);
            ldsm4(b[3], Bc + (wn + 48 + srow) * 40 + kk + scol);
            #pragma unroll
            for (int f = 0; f < 2; f++)
                #pragma unroll
                for (int n = 0; n < 8; n++)
                    mma16816(acc[f][n], a[f], b[n >> 1][n & 1], b[n >> 1][(n & 1) + 2]);
        }
        __syncthreads();
        sb ^= 1;
    }

    // ---- epilogue ----
    const int grp = lane >> 2, tg = lane & 3;

    if (MODE == 1) {
        if (j0 < 256) {
            bf16* Cs = (bf16*)raw;   // [128][136]
            #pragma unroll
            for (int f = 0; f < 2; f++)
                #pragma unroll
                for (int half = 0; half < 2; half++) {
                    const int mm = wm + f * 16 + grp + half * 8;
                    #pragma unroll
                    for (int n = 0; n < 8; n++) {
                        const int jj = wn + n * 8 + tg * 2;
                        Cs[mm * 136 + jj]     = __float2bfloat16(acc[f][n][half * 2 + 0]);
                        Cs[mm * 136 + jj + 1] = __float2bfloat16(acc[f][n][half * 2 + 1]);
                    }
                }
            __syncthreads();
            const int c = tid & 127, sqb = tid >> 7;
            const int gdi = j0 + c;
            const int wb = (r * 256 + gdi) * 4;
            const float w0 = conv_w[wb], w1 = conv_w[wb + 1], w2 = conv_w[wb + 2], w3 = conv_w[wb + 3];
            const float cb = conv_b[r * 256 + gdi];
            #pragma unroll
            for (int ss = 0; ss < 2; ss++) {
                const int sq = sqb + ss * 2;
                float x0 = 0.f, x1 = 0.f, x2 = 0.f;
                bf16* dst = g_xc + ((size_t)r * VV + m0 + sq * 32) * 256 + gdi;
                #pragma unroll
                for (int t = 0; t < 32; t++) {
                    const float xv = __bfloat162float(Cs[(sq * 32 + t) * 136 + c]);
                    const float s = x0 * w0 + x1 * w1 + x2 * w2 + xv * w3 + cb;
                    dst[(size_t)t * 256] = __float2bfloat16(siluf(s));
                    x0 = x1; x1 = x2; x2 = xv;
                }
            }
        } else {
            #pragma unroll
            for (int f = 0; f < 2; f++)
                #pragma unroll
                for (int half = 0; half < 2; half++) {
                    const int m = m0 + wm + f * 16 + grp + half * 8;
                    #pragma unroll
                    for (int n = 0; n < 8; n++) {
                        const int j = j0 - 256 + wn + n * 8 + tg * 2;
                        __nv_bfloat162 v;
                        v.x = __float2bfloat16(siluf(acc[f][n][half * 2 + 0]));
                        v.y = __float2bfloat16(siluf(acc[f][n][half * 2 + 1]));
                        *(__nv_bfloat162*)&g_z[((size_t)r * VV + m) * 256 + j] = v;
                    }
                }
        }
        return;
    }

    // MODE 2: scatter per-branch contribution into g_yb[r][vox][128]
    #pragma unroll
    for (int f = 0; f < 2; f++) {
        #pragma unroll
        for (int half = 0; half < 2; half++) {
            const int m = m0 + wm + f * 16 + grp + half * 8;
            const int vox = vox_of(r, m);
            #pragma unroll
            for (int n = 0; n < 8; n++) {
                const int j = j0 + wn + n * 8 + tg * 2;
                __nv_bfloat162 v;
                v.x = __float2bfloat16(acc[f][n][half * 2 + 0]);
                v.y = __float2bfloat16(acc[f][n][half * 2 + 1]);
                *(__nv_bfloat162*)&g_yb[((size_t)r * VV + vox) * 128 + j] = v;
            }
        }
    }
}

// ---------------- elementwise: g_f = gelu(sum_r contrib_r + fb) ----------------
__global__ __launch_bounds__(256) void sumgelu_kernel(const float* __restrict__ fb) {
    const size_t e0 = ((size_t)blockIdx.x * 256 + threadIdx.x) * 8;
    const uint4 v0 = *(const uint4*)&g_yb[e0];
    const uint4 v1 = *(const uint4*)&g_yb[(size_t)VV * 128 + e0];
    const uint4 v2 = *(const uint4*)&g_yb[2ull * VV * 128 + e0];
    const int c0 = (int)(e0 & 127);
    const float4 b0 = *(const float4*)&fb[c0];
    const float4 b1 = *(const float4*)&fb[c0 + 4];

    const u32* p0 = (const u32*)&v0;
    const u32* p1 = (const u32*)&v1;
    const u32* p2 = (const u32*)&v2;
    u32 ov[4];
    const float bias[8] = {b0.x, b0.y, b0.z, b0.w, b1.x, b1.y, b1.z, b1.w};
    #pragma unroll
    for (int i = 0; i < 4; i++) {
        const float2 a = __bfloat1622float2(*(const __nv_bfloat162*)&p0[i]);
        const float2 b = __bfloat1622float2(*(const __nv_bfloat162*)&p1[i]);
        const float2 c = __bfloat1622float2(*(const __nv_bfloat162*)&p2[i]);
        float u0 = a.x + b.x + c.x + bias[2 * i];
        float u1 = a.y + b.y + c.y + bias[2 * i + 1];
        float g0 = 0.5f * u0 * (1.f + erff(u0 * 0.70710678118654752f));
        float g1 = 0.5f * u1 * (1.f + erff(u1 * 0.70710678118654752f));
        __nv_bfloat162 o; o.x = __float2bfloat16(g0); o.y = __float2bfloat16(g1);
        ov[i] = *(const u32*)&o;
    }
    *(uint4*)&g_f[e0] = make_uint4(ov[0], ov[1], ov[2], ov[3]);
}

// ======== 128x64-tile GEMM (MODEs 0,4), 3-stage pipeline; per-branch r ========
template <int MODE>
__global__ __launch_bounds__(256) void bgemm_kernel(
    int r, const float* __restrict__ bias, const float* __restrict__ resid, float* __restrict__ outp)
{
    constexpr int Kc = (MODE == 4) ? 128 : 256;
    constexpr int Nc = (MODE == 0) ? 40 : VV;
    constexpr int NSTAGE = Kc / 32;

    __shared__ __align__(16) bf16 As[3][128][40];
    __shared__ __align__(16) bf16 Bs[3][64][40];

    const int m0  = blockIdx.y * 128;
    const int j0  = blockIdx.x * 64;
    const int tid = threadIdx.x;
    const int lane = tid & 31, warp = tid >> 5;
    const int wm = (warp & 3) * 32, wn = (warp >> 2) * 32;

    const bf16* Abase = (MODE == 0) ? (g_xc + (size_t)r * VV * 256) : g_w_p;
    const bf16* Bbase = (MODE == 0) ? (g_w_xp + (size_t)r * 40 * 256) : g_f;

    const int lrow = tid >> 2;
    const int lk8  = (tid & 3) << 3;

    const bf16* arow0 = Abase + (size_t)(m0 + lrow) * Kc;
    const bf16* arow1 = Abase + (size_t)(m0 + lrow + 64) * Kc;
    const int bj = j0 + lrow;
    const bf16* brow = Bbase + (size_t)bj * Kc;
    const bool bvalid = (Nc % 64 == 0) || (bj < Nc);

    float acc[2][4][4];
    #pragma unroll
    for (int f = 0; f < 2; f++)
        #pragma unroll
        for (int n = 0; n < 4; n++)
            #pragma unroll
            for (int i = 0; i < 4; i++) acc[f][n][i] = 0.f;

    const int srow = lane & 15;
    const int scol = (lane >> 4) << 3;

    cpa16(&As[0][lrow     ][lk8], arow0 + lk8, true);
    cpa16(&As[0][lrow + 64][lk8], arow1 + lk8, true);
    cpa16(&Bs[0][lrow     ][lk8], brow  + lk8, bvalid);
    cpa_commit();
    cpa16(&As[1][lrow     ][lk8], arow0 + 32 + lk8, true);
    cpa16(&As[1][lrow + 64][lk8], arow1 + 32 + lk8, true);
    cpa16(&Bs[1][lrow     ][lk8], brow  + 32 + lk8, bvalid);
    cpa_commit();

    #pragma unroll
    for (int st = 0; st < NSTAGE; st++) {
        cpa_wait<1>();
        __syncthreads();
        const int kn = (st + 2) * 32;
        const int bnext = (st + 2) % 3;
        if (kn < Kc) {
            cpa16(&As[bnext][lrow     ][lk8], arow0 + kn + lk8, true);
            cpa16(&As[bnext][lrow + 64][lk8], arow1 + kn + lk8, true);
            cpa16(&Bs[bnext][lrow     ][lk8], brow  + kn + lk8, bvalid);
        }
        cpa_commit();
        const int bc = st % 3;
        #pragma unroll
        for (int kk = 0; kk < 32; kk += 16) {
            u32 a[2][4], b[2][4];
            ldsm4(a[0], &As[bc][wm +      srow][kk + scol]);
            ldsm4(a[1], &As[bc][wm + 16 + srow][kk + scol]);
            ldsm4(b[0], &Bs[bc][wn +      srow][kk + scol]);
            ldsm4(b[1], &Bs[bc][wn + 16 + srow][kk + scol]);
            #pragma unroll
            for (int f = 0; f < 2; f++)
                #pragma unroll
                for (int n = 0; n < 4; n++)
                    mma16816(acc[f][n], a[f], b[n >> 1][n & 1], b[n >> 1][(n & 1) + 2]);
        }
    }

    const int grp = lane >> 2, tg = lane & 3;
    #pragma unroll
    for (int f = 0; f < 2; f++) {
        #pragma unroll
        for (int half = 0; half < 2; half++) {
            const int m = m0 + wm + f * 16 + grp + half * 8;
            #pragma unroll
            for (int n = 0; n < 4; n++) {
                const int j = j0 + wn + n * 8 + tg * 2;
                const float c0 = acc[f][n][half * 2 + 0];
                const float c1 = acc[f][n][half * 2 + 1];
                if (MODE == 0) {
                    if (j < 40)
                        *(float2*)&g_dbl[(size_t)r * VV * 40 + (size_t)m * 40 + j] = make_float2(c0, c1);
                } else {
                    float2 rd = *(const float2*)&resid[(size_t)m * VV + j];
                    *(float2*)&outp[(size_t)m * VV + j] =
                        make_float2(c0 + bias[m] + rd.x, c1 + bias[m] + rd.y);
                }
            }
        }
    }
}

// ---------------- dt + selective scan + gate (round-7 proven); per-branch r ----------------
__global__ __launch_bounds__(256) void scan_kernel(
    int r, const float* __restrict__ dt_w, const float* __restrict__ dt_b,
    const float* __restrict__ A_log, const float* __restrict__ Dparam)
{
    __shared__ __align__(16) float sm[LSEQ * 40];
    const int n = blockIdx.x, di = threadIdx.x;

    const float* dblp = g_dbl + (size_t)(r * NSEQ + n) * LSEQ * 40;
    #pragma unroll
    for (int e = di; e < LSEQ * 10; e += 256)
        ((float4*)sm)[e] = ((const float4*)dblp)[e];
    __syncthreads();

    float dtw[8];
    #pragma unroll
    for (int k = 0; k < 8; k++) dtw[k] = dt_w[(r * 256 + di) * 8 + k];
    const float dtb = dt_b[r * 256 + di];
    const float Dpv = Dparam[r * 256 + di];

    const float Av0 = -__expf(A_log[(r * 256 + di) * 16]);
    bool ap = true;
    #pragma unroll
    for (int s = 1; s < 16; s++) {
        const float As = -__expf(A_log[(r * 256 + di) * 16 + s]);
        ap = ap && (fabsf(As - (float)(s + 1) * Av0) <= 1e-4f * fabsf(As) + 1e-6f);
    }

    float h[16];
    #pragma unroll
    for (int s = 0; s < 16; s++) h[s] = 0.f;

    const bf16* xcp = g_xc   + ((size_t)(r * NSEQ + n) * LSEQ) * 256 + di;
    const bf16* zp  = g_z    + ((size_t)(r * NSEQ + n) * LSEQ) * 256 + di;
    bf16*       yp  = g_ymid + ((size_t)(r * NSEQ + n) * LSEQ) * 256 + di;

    if (ap) {
        #pragma unroll 4
        for (int t = 0; t < LSEQ; t++) {
            const float4* ds4 = (const float4*)(sm + t * 40);
            const float4 d0 = ds4[0], d1 = ds4[1];
            float xl = dtb;
            xl = fmaf(d0.x, dtw[0], xl); xl = fmaf(d0.y, dtw[1], xl);
            xl = fmaf(d0.z, dtw[2], xl); xl = fmaf(d0.w, dtw[3], xl);
            xl = fmaf(d1.x, dtw[4], xl); xl = fmaf(d1.y, dtw[5], xl);
            xl = fmaf(d1.z, dtw[6], xl); xl = fmaf(d1.w, dtw[7], xl);
            const float dt = (xl > 15.f) ? xl : __logf(1.f + __expf(xl));

            const float xcv = __bfloat162float(xcp[(size_t)t * 256]);
            const float sz  = __bfloat162float(zp [(size_t)t * 256]);
            const float du  = dt * xcv;

            const float4 B0 = ds4[2], B1 = ds4[3], B2 = ds4[4], B3 = ds4[5];
            const float4 C0 = ds4[6], C1 = ds4[7], C2 = ds4[8], C3 = ds4[9];

            const float p1 = __expf(dt * Av0);
            const float p2 = p1 * p1;
            const float p4 = p2 * p2;
            float pa = p1, pb = p2, pc = p2 * p1, pd = p4;

            h[0]  = fmaf(pa, h[0],  du * B0.x);
            h[1]  = fmaf(pb, h[1],  du * B0.y);
            h[2]  = fmaf(pc, h[2],  du * B0.z);
            h[3]  = fmaf(pd, h[3],  du * B0.w);
            pa *= p4; pb *= p4; pc *= p4; pd *= p4;
            h[4]  = fmaf(pa, h[4],  du * B1.x);
            h[5]  = fmaf(pb, h[5],  du * B1.y);
            h[6]  = fmaf(pc, h[6],  du * B1.z);
            h[7]  = fmaf(pd, h[7],  du * B1.w);
            pa *= p4; pb *= p4; pc *= p4; pd *= p4;
            h[8]  = fmaf(pa, h[8],  du * B2.x);
            h[9]  = fmaf(pb, h[9],  du * B2.y);
            h[10] = fmaf(pc, h[10], du * B2.z);
            h[11] = fmaf(pd, h[11], du * B2.w);
            pa *= p4; pb *= p4; pc *= p4; pd *= p4;
            h[12] = fmaf(pa, h[12], du * B3.x);
            h[13] = fmaf(pb, h[13], du * B3.y);
            h[14] = fmaf(pc, h[14], du * B3.z);
            h[15] = fmaf(pd, h[15], du * B3.w);

            float y0 = h[0] * C0.x;  y0 = fmaf(h[1],  C0.y, y0);
            y0 = fmaf(h[2],  C0.z, y0); y0 = fmaf(h[3],  C0.w, y0);
            float y1 = h[4] * C1.x;  y1 = fmaf(h[5],  C1.y, y1);
            y1 = fmaf(h[6],  C1.z, y1); y1 = fmaf(h[7],  C1.w, y1);
            float y2 = h[8] * C2.x;  y2 = fmaf(h[9],  C2.y, y2);
            y2 = fmaf(h[10], C2.z, y2); y2 = fmaf(h[11], C2.w, y2);
            float y3 = h[12] * C3.x; y3 = fmaf(h[13], C3.y, y3);
            y3 = fmaf(h[14], C3.z, y3); y3 = fmaf(h[15], C3.w, y3);
            const float y = (y0 + y1) + (y2 + y3);

            yp[(size_t)t * 256] = __float2bfloat16(fmaf(Dpv, xcv, y) * sz);
        }
    } else {
        for (int t = 0; t < LSEQ; t++) {
            const float* row = sm + t * 40;
            float xl = dtb;
            #pragma unroll
            for (int k = 0; k < 8; k++) xl = fmaf(row[k], dtw[k], xl);
            const float dt = (xl > 15.f) ? xl : log1pf(__expf(xl));
            const float xcv = __bfloat162float(xcp[(size_t)t * 256]);
            const float sz  = __bfloat162float(zp [(size_t)t * 256]);
            const float du  = dt * xcv;
            float y = 0.f;
            #pragma unroll
            for (int s = 0; s < 16; s++) {
                const float Avs = -__expf(A_log[(r * 256 + di) * 16 + s]);
                const float dA = __expf(dt * Avs);
                h[s] = fmaf(dA, h[s], du * row[8 + s]);
                y = fmaf(h[s], row[24 + s], y);
            }
            yp[(size_t)t * 256] = __float2bfloat16(fmaf(Dpv, xcv, y) * sz);
        }
    }
}

// ---------------- launch: 3-stream branch pipeline (capture-safe fork/join) ----------------
extern "C" void kernel_launch(void* const* d_in, const int* in_sizes, int n_in,
                              void* d_out, int out_size)
{
    const float* x      = (const float*)d_in[0];
    const float* ng     = (const float*)d_in[1];
    const float* nb     = (const float*)d_in[2];
    const float* in_w   = (const float*)d_in[3];
    const float* conv_w = (const float*)d_in[4];
    const float* conv_b = (const float*)d_in[5];
    const float* xp_w   = (const float*)d_in[6];
    const float* dt_w   = (const float*)d_in[7];
    const float* dt_b   = (const float*)d_in[8];
    const float* A_log  = (const float*)d_in[9];
    const float* Dparam = (const float*)d_in[10];
    const float* out_w  = (const float*)d_in[11];
    const float* fw     = (const float*)d_in[12];
    const float* fb     = (const float*)d_in[13];
    const float* pw     = (const float*)d_in[14];
    const float* pb     = (const float*)d_in[15];
    float* out = (float*)d_out;

    static cudaStream_t s1 = nullptr, s2 = nullptr;
    static cudaEvent_t evFork, evCvt, evLn, evWc, evR1, evR2;
    if (s1 == nullptr) {
        cudaStreamCreateWithFlags(&s1, cudaStreamNonBlocking);
        cudaStreamCreateWithFlags(&s2, cudaStreamNonBlocking);
        cudaEventCreateWithFlags(&evFork, cudaEventDisableTiming);
        cudaEventCreateWithFlags(&evCvt,  cudaEventDisableTiming);
        cudaEventCreateWithFlags(&evLn,   cudaEventDisableTiming);
        cudaEventCreateWithFlags(&evWc,   cudaEventDisableTiming);
        cudaEventCreateWithFlags(&evR1,   cudaEventDisableTiming);
        cudaEventCreateWithFlags(&evR2,   cudaEventDisableTiming);
    }

    // fork
    cudaEventRecord(evFork, 0);
    cudaStreamWaitEvent(s1, evFork, 0);
    cudaStreamWaitEvent(s2, evFork, 0);

    // s1: weight convert ; s2: combined-weight build ; origin: layernorm
    cvt_kernel<<<(3 * 512 * 128 + 255) / 256, 256, 0, s1>>>(in_w, xp_w, pw);
    cudaEventRecord(evCvt, s1);
    wcomb_kernel<<<dim3(128, 3), 256, 0, s2>>>(fw, out_w);
    cudaEventRecord(evWc, s2);
    ln_kernel<<<VV / 32, 256>>>(x, ng, nb);
    cudaEventRecord(evLn, 0);

    // cross deps: every chain needs cvt(in/xp weights), ln(xn), wc(combined weights for its out_proj)
    cudaStreamWaitEvent(0,  evCvt, 0);
    cudaStreamWaitEvent(0,  evWc,  0);
    cudaStreamWaitEvent(s1, evLn,  0);
    cudaStreamWaitEvent(s1, evWc,  0);
    cudaStreamWaitEvent(s2, evCvt, 0);
    cudaStreamWaitEvent(s2, evLn,  0);

    // branch chains
    cudaStream_t bs[3] = { (cudaStream_t)0, s1, s2 };
    for (int r = 0; r < 3; r++) {
        cudaStream_t s = bs[r];
        bgemm128_kernel<1><<<dim3(4, VV / 128), 256, 0, s>>>(r, conv_w, conv_b);  // in_proj+conv+silu
        bgemm_kernel<0><<<dim3(1, VV / 128), 256, 0, s>>>(r, nullptr, nullptr, nullptr); // x_proj
        scan_kernel<<<dim3(NSEQ), 256, 0, s>>>(r, dt_w, dt_b, A_log, Dparam);     // scan
        bgemm128_kernel<2><<<dim3(1, VV / 128), 256, 0, s>>>(r, nullptr, nullptr); // out_proj x W'
    }
    cudaEventRecord(evR1, s1);
    cudaEventRecord(evR2, s2);

    // join, then sum+gelu and final proj
    cudaStreamWaitEvent(0, evR1, 0);
    cudaStreamWaitEvent(0, evR2, 0);
    sumgelu_kernel<<<VV * 128 / (256 * 8), 256>>>(fb);                 // fusion as elementwise
    bgemm_kernel<4><<<dim3(VV / 64, 1), 256>>>(0, pb, x, out);         // proj+residual
}

// round 14
// speedup vs baseline: 1.0864x; 1.0864x over previous
#include <cuda_runtime.h>
#include <cuda_bf16.h>
#include <cstdint>
#include <math.h>

typedef unsigned int u32;

#define VV    32768
#define NSEQ  1024
#define LSEQ  32
#define CD    128
#define DIc   256

typedef __nv_bfloat16 bf16;

// ---------------- scratch (device globals: allocation-free) ----------------
__device__ __align__(16) bf16  g_xn  [(size_t)VV * CD];
__device__ __align__(16) bf16  g_z   [3ull * VV * DIc];
__device__ __align__(16) bf16  g_xc  [3ull * VV * DIc];
__device__ __align__(16) bf16  g_ymid[3ull * VV * DIc];
__device__ __align__(16) bf16  g_yb  [(size_t)VV * 384];   // [3][VV][128] per-branch proj contributions
__device__ __align__(16) bf16  g_f   [(size_t)VV * CD];

__device__ __align__(16) bf16 g_w_in [3 * 512 * 128];
__device__ __align__(16) bf16 g_w_xp [3 * 40 * 256];
__device__ __align__(16) bf16 g_w_c  [3 * 128 * 256];      // combined Wf_r @ Wout_r
__device__ __align__(16) bf16 g_w_p  [128 * 128];

__device__ __forceinline__ int vox_of(int r, int m) {
    int n = m >> 5, t = m & 31;
    if (r == 0) return (t << 10) + n;
    if (r == 1) return ((n >> 5) << 10) + (t << 5) + (n & 31);
    return (n << 5) + t;
}

// ---------------- weight convert fp32 -> bf16 ----------------
__global__ __launch_bounds__(256) void cvt_kernel(
    const float* __restrict__ in_w, const float* __restrict__ xp_w,
    const float* __restrict__ pw)
{
    const int i = blockIdx.x * 256 + threadIdx.x;
    if (i < 3 * 512 * 128) g_w_in[i] = __float2bfloat16(in_w[i]);
    if (i < 3 * 40 * 256)  g_w_xp[i] = __float2bfloat16(xp_w[i]);
    if (i < 128 * 128)     g_w_p[i]  = __float2bfloat16(pw[i]);
}

// ---------------- combined weight: W'_r = Wf[:, r*128:+128] @ Wout_r (fp32) ----------------
__global__ __launch_bounds__(256) void wcomb_kernel(
    const float* __restrict__ fw, const float* __restrict__ out_w)
{
    const int r = blockIdx.y, o = blockIdx.x, k = threadIdx.x;
    float s = 0.f;
    #pragma unroll 8
    for (int j = 0; j < 128; j++)
        s = fmaf(fw[o * 384 + r * 128 + j], out_w[((size_t)r * 128 + j) * 256 + k], s);
    g_w_c[((size_t)r * 128 + o) * 256 + k] = __float2bfloat16(s);
}

// ---------------- LayerNorm ----------------
__global__ __launch_bounds__(256) void ln_kernel(
    const float* __restrict__ x, const float* __restrict__ g, const float* __restrict__ b)
{
    __shared__ float sm[128][33];
    __shared__ float smu[32], srs[32];
    const int v0 = blockIdx.x * 32;
    const int tid = threadIdx.x;

    #pragma unroll
    for (int it = 0; it < 16; it++) {
        int e = it * 256 + tid;
        int c = e >> 5, vi = e & 31;
        sm[c][vi] = x[(size_t)c * VV + v0 + vi];
    }
    __syncthreads();
    if (tid < 32) {
        float s = 0.f, s2 = 0.f;
        #pragma unroll 8
        for (int c = 0; c < 128; c++) { float v = sm[c][tid]; s += v; s2 += v * v; }
        float m = s * (1.f / 128.f);
        float var = s2 * (1.f / 128.f) - m * m;
        smu[tid] = m;
        srs[tid] = rsqrtf(var + 1e-5f);
    }
    __syncthreads();
    #pragma unroll
    for (int it = 0; it < 16; it++) {
        int e = it * 256 + tid;
        int c = e & 127, vi = e >> 7;
        float v = (sm[c][vi] - smu[vi]) * srs[vi] * g[c] + b[c];
        g_xn[(size_t)(v0 + vi) * 128 + c] = __float2bfloat16(v);
    }
}

// ---------------- tensor-core / async-copy helpers ----------------
__device__ __forceinline__ void ldsm4(u32* r, const void* p) {
    u32 addr = (u32)__cvta_generic_to_shared(p);
    asm volatile("ldmatrix.sync.aligned.m8n8.x4.shared.b16 {%0,%1,%2,%3}, [%4];"
        : "=r"(r[0]), "=r"(r[1]), "=r"(r[2]), "=r"(r[3]) : "r"(addr));
}
__device__ __forceinline__ void mma16816(float* c, const u32* a, u32 b0, u32 b1) {
    asm volatile("mma.sync.aligned.m16n8k16.row.col.f32.bf16.bf16.f32 "
        "{%0,%1,%2,%3}, {%4,%5,%6,%7}, {%8,%9}, {%0,%1,%2,%3};"
        : "+f"(c[0]), "+f"(c[1]), "+f"(c[2]), "+f"(c[3])
        : "r"(a[0]), "r"(a[1]), "r"(a[2]), "r"(a[3]), "r"(b0), "r"(b1));
}
__device__ __forceinline__ void cpa16(void* dst, const void* src, bool pred) {
    u32 d = (u32)__cvta_generic_to_shared(dst);
    int sz = pred ? 16 : 0;
    asm volatile("cp.async.ca.shared.global [%0], [%1], 16, %2;" :: "r"(d), "l"(src), "r"(sz));
}
__device__ __forceinline__ void cpa_commit() { asm volatile("cp.async.commit_group;"); }
template <int N> __device__ __forceinline__ void cpa_wait() {
    asm volatile("cp.async.wait_group %0;" :: "n"(N));
}
__device__ __forceinline__ float siluf(float s) { return s / (1.f + __expf(-s)); }

// ======== 128x128-tile GEMM (MODEs 1,2), 2-stage pipeline; per-branch r ========
template <int MODE>
__global__ __launch_bounds__(256) void bgemm128_kernel(
    int r, const float* __restrict__ conv_w, const float* __restrict__ conv_b)
{
    constexpr int Kc = (MODE == 1) ? 128 : 256;
    constexpr int NSTAGE = Kc / 32;

    __shared__ __align__(16) char raw[40960];
    bf16* As = (bf16*)raw;
    bf16* Bs = As + 2 * 128 * 40;

    const int m0  = blockIdx.y * 128;
    const int j0  = blockIdx.x * 128;
    const int tid = threadIdx.x;
    const int lane = tid & 31, warp = tid >> 5;
    const int wm = (warp & 3) * 32, wn = (warp >> 2) * 64;

    const bf16* Bbase = (MODE == 1) ? (g_w_in + (size_t)r * 512 * 128)
                                    : (g_w_c  + (size_t)r * 128 * 256);

    const int lrow = tid >> 2;
    const int lk8  = (tid & 3) << 3;

    const bf16 *arow0, *arow1;
    if (MODE == 1) {
        arow0 = g_xn + (size_t)vox_of(r, m0 + lrow) * 128;
        arow1 = g_xn + (size_t)vox_of(r, m0 + lrow + 64) * 128;
    } else {
        arow0 = g_ymid + (size_t)r * VV * 256 + (size_t)(m0 + lrow) * 256;
        arow1 = g_ymid + (size_t)r * VV * 256 + (size_t)(m0 + lrow + 64) * 256;
    }
    const bf16* brow0 = Bbase + (size_t)(j0 + lrow) * Kc;
    const bf16* brow1 = Bbase + (size_t)(j0 + lrow + 64) * Kc;

    float acc[2][8][4];
    #pragma unroll
    for (int f = 0; f < 2; f++)
        #pragma unroll
        for (int n = 0; n < 8; n++)
            #pragma unroll
            for (int i = 0; i < 4; i++) acc[f][n][i] = 0.f;

    const int srow = lane & 15;
    const int scol = (lane >> 4) << 3;

    cpa16(As + (lrow      ) * 40 + lk8, arow0 + lk8, true);
    cpa16(As + (lrow + 64 ) * 40 + lk8, arow1 + lk8, true);
    cpa16(Bs + (lrow      ) * 40 + lk8, brow0 + lk8, true);
    cpa16(Bs + (lrow + 64 ) * 40 + lk8, brow1 + lk8, true);
    cpa_commit();

    int sb = 0;
    #pragma unroll
    for (int st = 0; st < NSTAGE; st++) {
        const int kn = (st + 1) * 32;
        if (kn < Kc) {
            bf16* Ad = As + (sb ^ 1) * 128 * 40;
            bf16* Bd = Bs + (sb ^ 1) * 128 * 40;
            cpa16(Ad + (lrow     ) * 40 + lk8, arow0 + kn + lk8, true);
            cpa16(Ad + (lrow + 64) * 40 + lk8, arow1 + kn + lk8, true);
            cpa16(Bd + (lrow     ) * 40 + lk8, brow0 + kn + lk8, true);
            cpa16(Bd + (lrow + 64) * 40 + lk8, brow1 + kn + lk8, true);
        }
        cpa_commit();
        cpa_wait<1>();
        __syncthreads();
        const bf16* Ac = As + sb * 128 * 40;
        const bf16* Bc = Bs + sb * 128 * 40;
        #pragma unroll
        for (int kk = 0; kk < 32; kk += 16) {
            u32 a[2][4], b[4][4];
            ldsm4(a[0], Ac + (wm +      srow) * 40 + kk + scol);
            ldsm4(a[1], Ac + (wm + 16 + srow) * 40 + kk + scol);
            ldsm4(b[0], Bc + (wn +      srow) * 40 + kk + scol);
            ldsm4(b[1], Bc + (wn + 16 + srow) * 40 + kk + scol);
            ldsm4(b[2], Bc + (wn + 32 + srow) * 40 + kk + scol);
            ldsm4(b[3], Bc + (wn + 48 + srow) * 40 + kk + scol);
            #pragma unroll
            for (int f = 0; f < 2; f++)
                #pragma unroll
                for (int n = 0; n < 8; n++)
                    mma16816(acc[f][n], a[f], b[n >> 1][n & 1], b[n >> 1][(n & 1) + 2]);
        }
        __syncthreads();
        sb ^= 1;
    }

    const int grp = lane >> 2, tg = lane & 3;

    if (MODE == 1) {
        if (j0 < 256) {
            bf16* Cs = (bf16*)raw;   // [128][136]
            #pragma unroll
            for (int f = 0; f < 2; f++)
                #pragma unroll
                for (int half = 0; half < 2; half++) {
                    const int mm = wm + f * 16 + grp + half * 8;
                    #pragma unroll
                    for (int n = 0; n < 8; n++) {
                        const int jj = wn + n * 8 + tg * 2;
                        Cs[mm * 136 + jj]     = __float2bfloat16(acc[f][n][half * 2 + 0]);
                        Cs[mm * 136 + jj + 1] = __float2bfloat16(acc[f][n][half * 2 + 1]);
                    }
                }
            __syncthreads();
            const int c = tid & 127, sqb = tid >> 7;
            const int gdi = j0 + c;
            const int wb = (r * 256 + gdi) * 4;
            const float w0 = conv_w[wb], w1 = conv_w[wb + 1], w2 = conv_w[wb + 2], w3 = conv_w[wb + 3];
            const float cb = conv_b[r * 256 + gdi];
            #pragma unroll
            for (int ss = 0; ss < 2; ss++) {
                const int sq = sqb + ss * 2;
                float x0 = 0.f, x1 = 0.f, x2 = 0.f;
                bf16* dst = g_xc + ((size_t)r * VV + m0 + sq * 32) * 256 + gdi;
                #pragma unroll
                for (int t = 0; t < 32; t++) {
                    const float xv = __bfloat162float(Cs[(sq * 32 + t) * 136 + c]);
                    const float s = x0 * w0 + x1 * w1 + x2 * w2 + xv * w3 + cb;
                    dst[(size_t)t * 256] = __float2bfloat16(siluf(s));
                    x0 = x1; x1 = x2; x2 = xv;
                }
            }
        } else {
            #pragma unroll
            for (int f = 0; f < 2; f++)
                #pragma unroll
                for (int half = 0; half < 2; half++) {
                    const int m = m0 + wm + f * 16 + grp + half * 8;
                    #pragma unroll
                    for (int n = 0; n < 8; n++) {
                        const int j = j0 - 256 + wn + n * 8 + tg * 2;
                        __nv_bfloat162 v;
                        v.x = __float2bfloat16(siluf(acc[f][n][half * 2 + 0]));
                        v.y = __float2bfloat16(siluf(acc[f][n][half * 2 + 1]));
                        *(__nv_bfloat162*)&g_z[((size_t)r * VV + m) * 256 + j] = v;
                    }
                }
        }
        return;
    }

    // MODE 2: scatter per-branch contribution into g_yb[r][vox][128]
    #pragma unroll
    for (int f = 0; f < 2; f++) {
        #pragma unroll
        for (int half = 0; half < 2; half++) {
            const int m = m0 + wm + f * 16 + grp + half * 8;
            const int vox = vox_of(r, m);
            #pragma unroll
            for (int n = 0; n < 8; n++) {
                const int j = j0 + wn + n * 8 + tg * 2;
                __nv_bfloat162 v;
                v.x = __float2bfloat16(acc[f][n][half * 2 + 0]);
                v.y = __float2bfloat16(acc[f][n][half * 2 + 1]);
                *(__nv_bfloat162*)&g_yb[((size_t)r * VV + vox) * 128 + j] = v;
            }
        }
    }
}

// ---------------- elementwise: g_f = gelu(sum_r contrib_r + fb) ----------------
__global__ __launch_bounds__(256) void sumgelu_kernel(const float* __restrict__ fb) {
    const size_t e0 = ((size_t)blockIdx.x * 256 + threadIdx.x) * 8;
    const uint4 v0 = *(const uint4*)&g_yb[e0];
    const uint4 v1 = *(const uint4*)&g_yb[(size_t)VV * 128 + e0];
    const uint4 v2 = *(const uint4*)&g_yb[2ull * VV * 128 + e0];
    const int c0 = (int)(e0 & 127);
    const float4 b0 = *(const float4*)&fb[c0];
    const float4 b1 = *(const float4*)&fb[c0 + 4];

    const u32* p0 = (const u32*)&v0;
    const u32* p1 = (const u32*)&v1;
    const u32* p2 = (const u32*)&v2;
    u32 ov[4];
    const float bias[8] = {b0.x, b0.y, b0.z, b0.w, b1.x, b1.y, b1.z, b1.w};
    #pragma unroll
    for (int i = 0; i < 4; i++) {
        const float2 a = __bfloat1622float2(*(const __nv_bfloat162*)&p0[i]);
        const float2 b = __bfloat1622float2(*(const __nv_bfloat162*)&p1[i]);
        const float2 c = __bfloat1622float2(*(const __nv_bfloat162*)&p2[i]);
        float u0 = a.x + b.x + c.x + bias[2 * i];
        float u1 = a.y + b.y + c.y + bias[2 * i + 1];
        float g0 = 0.5f * u0 * (1.f + erff(u0 * 0.70710678118654752f));
        float g1 = 0.5f * u1 * (1.f + erff(u1 * 0.70710678118654752f));
        __nv_bfloat162 o; o.x = __float2bfloat16(g0); o.y = __float2bfloat16(g1);
        ov[i] = *(const u32*)&o;
    }
    *(uint4*)&g_f[e0] = make_uint4(ov[0], ov[1], ov[2], ov[3]);
}

// ======== final proj GEMM (128x64 tile, 3-stage pipeline) ========
__global__ __launch_bounds__(256) void proj_kernel(
    const float* __restrict__ bias, const float* __restrict__ resid, float* __restrict__ outp)
{
    constexpr int Kc = 128;

    __shared__ __align__(16) bf16 As[3][128][40];
    __shared__ __align__(16) bf16 Bs[3][64][40];

    const int m0  = blockIdx.y * 128;
    const int j0  = blockIdx.x * 64;
    const int tid = threadIdx.x;
    const int lane = tid & 31, warp = tid >> 5;
    const int wm = (warp & 3) * 32, wn = (warp >> 2) * 32;

    const int lrow = tid >> 2;
    const int lk8  = (tid & 3) << 3;

    const bf16* arow0 = g_w_p + (size_t)(m0 + lrow) * Kc;
    const bf16* arow1 = g_w_p + (size_t)(m0 + lrow + 64) * Kc;
    const bf16* brow  = g_f   + (size_t)(j0 + lrow) * Kc;

    float acc[2][4][4];
    #pragma unroll
    for (int f = 0; f < 2; f++)
        #pragma unroll
        for (int n = 0; n < 4; n++)
            #pragma unroll
            for (int i = 0; i < 4; i++) acc[f][n][i] = 0.f;

    const int srow = lane & 15;
    const int scol = (lane >> 4) << 3;

    cpa16(&As[0][lrow     ][lk8], arow0 + lk8, true);
    cpa16(&As[0][lrow + 64][lk8], arow1 + lk8, true);
    cpa16(&Bs[0][lrow     ][lk8], brow  + lk8, true);
    cpa_commit();
    cpa16(&As[1][lrow     ][lk8], arow0 + 32 + lk8, true);
    cpa16(&As[1][lrow + 64][lk8], arow1 + 32 + lk8, true);
    cpa16(&Bs[1][lrow     ][lk8], brow  + 32 + lk8, true);
    cpa_commit();

    #pragma unroll
    for (int st = 0; st < 4; st++) {
        cpa_wait<1>();
        __syncthreads();
        const int kn = (st + 2) * 32;
        const int bnext = (st + 2) % 3;
        if (kn < Kc) {
            cpa16(&As[bnext][lrow     ][lk8], arow0 + kn + lk8, true);
            cpa16(&As[bnext][lrow + 64][lk8], arow1 + kn + lk8, true);
            cpa16(&Bs[bnext][lrow     ][lk8], brow  + kn + lk8, true);
        }
        cpa_commit();
        const int bc = st % 3;
        #pragma unroll
        for (int kk = 0; kk < 32; kk += 16) {
            u32 a[2][4], b[2][4];
            ldsm4(a[0], &As[bc][wm +      srow][kk + scol]);
            ldsm4(a[1], &As[bc][wm + 16 + srow][kk + scol]);
            ldsm4(b[0], &Bs[bc][wn +      srow][kk + scol]);
            ldsm4(b[1], &Bs[bc][wn + 16 + srow][kk + scol]);
            #pragma unroll
            for (int f = 0; f < 2; f++)
                #pragma unroll
                for (int n = 0; n < 4; n++)
                    mma16816(acc[f][n], a[f], b[n >> 1][n & 1], b[n >> 1][(n & 1) + 2]);
        }
    }

    const int grp = lane >> 2, tg = lane & 3;
    #pragma unroll
    for (int f = 0; f < 2; f++) {
        #pragma unroll
        for (int half = 0; half < 2; half++) {
            const int m = m0 + wm + f * 16 + grp + half * 8;
            #pragma unroll
            for (int n = 0; n < 4; n++) {
                const int j = j0 + wn + n * 8 + tg * 2;
                float2 rd = *(const float2*)&resid[(size_t)m * VV + j];
                *(float2*)&outp[(size_t)m * VV + j] =
                    make_float2(acc[f][n][half * 2] + bias[m] + rd.x,
                                acc[f][n][half * 2 + 1] + bias[m] + rd.y);
            }
        }
    }
}

// ======== fused x_proj GEMM + dt + selective scan + gate ========
// One block per (sequence, branch). Phase 1: dbl = xc_tile @ Wxp^T via mma
// (M=32, N=40 pad 48, K=256) into fp32 smem. Phase 2: round-7 scan, dbl and
// xc both read from smem.
__global__ __launch_bounds__(256) void xscan_kernel(
    int r, const float* __restrict__ dt_w, const float* __restrict__ dt_b,
    const float* __restrict__ A_log, const float* __restrict__ Dparam)
{
    __shared__ __align__(16) bf16  Axc[32 * 264];   // xc tile [t][di], pad 264
    __shared__ __align__(16) bf16  Bxp[48 * 264];   // Wxp rows [j][k], rows 40-47 garbage
    __shared__ __align__(16) float dsm[32 * 44];    // dbl fp32 [t][j], pad 44

    const int n = blockIdx.x, tid = threadIdx.x;
    const int lane = tid & 31, warp = tid >> 5;

    const bf16* asrc = g_xc + ((size_t)(r * NSEQ + n) * LSEQ) * 256;
    #pragma unroll
    for (int e = tid; e < 1024; e += 256) {            // 32 rows x 32 chunks
        const int row = e >> 5, c8 = (e & 31) << 3;
        cpa16(&Axc[row * 264 + c8], asrc + row * 256 + c8, true);
    }
    const bf16* bsrc = g_w_xp + (size_t)r * 40 * 256;
    #pragma unroll
    for (int e = tid; e < 1280; e += 256) {            // 40 rows x 32 chunks
        const int row = e >> 5, c8 = (e & 31) << 3;
        cpa16(&Bxp[row * 264 + c8], bsrc + row * 256 + c8, true);
    }
    cpa_commit();
    cpa_wait<0>();
    __syncthreads();

    // ---- phase 1: GEMM on warps 0-5 (2 m-tiles x 3 n-pairs) ----
    if (warp < 6) {
        const int mt = (warp & 1) * 16;
        const int np = (warp >> 1) * 16;
        const int srow = lane & 15, scol = (lane >> 4) << 3;
        float acc[2][4];
        #pragma unroll
        for (int nn = 0; nn < 2; nn++)
            #pragma unroll
            for (int i = 0; i < 4; i++) acc[nn][i] = 0.f;
        #pragma unroll
        for (int k0 = 0; k0 < 256; k0 += 16) {
            u32 a[4], b[4];
            ldsm4(a, &Axc[(mt + srow) * 264 + k0 + scol]);
            ldsm4(b, &Bxp[(np + srow) * 264 + k0 + scol]);
            mma16816(acc[0], a, b[0], b[2]);
            mma16816(acc[1], a, b[1], b[3]);
        }
        const int grp = lane >> 2, tg = lane & 3;
        #pragma unroll
        for (int nn = 0; nn < 2; nn++) {
            const int j = np + nn * 8 + tg * 2;
            if (j < 40) {
                #pragma unroll
                for (int half = 0; half < 2; half++) {
                    const int m = mt + grp + half * 8;
                    dsm[m * 44 + j]     = acc[nn][half * 2 + 0];
                    dsm[m * 44 + j + 1] = acc[nn][half * 2 + 1];
                }
            }
        }
    }
    __syncthreads();

    // ---- phase 2: scan (round-7 proven body) ----
    const int di = tid;
    float dtw[8];
    #pragma unroll
    for (int k = 0; k < 8; k++) dtw[k] = dt_w[(r * 256 + di) * 8 + k];
    const float dtb = dt_b[r * 256 + di];
    const float Dpv = Dparam[r * 256 + di];

    const float Av0 = -__expf(A_log[(r * 256 + di) * 16]);
    bool ap = true;
    #pragma unroll
    for (int s = 1; s < 16; s++) {
        const float As = -__expf(A_log[(r * 256 + di) * 16 + s]);
        ap = ap && (fabsf(As - (float)(s + 1) * Av0) <= 1e-4f * fabsf(As) + 1e-6f);
    }

    float h[16];
    #pragma unroll
    for (int s = 0; s < 16; s++) h[s] = 0.f;

    const bf16* zp = g_z    + ((size_t)(r * NSEQ + n) * LSEQ) * 256 + di;
    bf16*       yp = g_ymid + ((size_t)(r * NSEQ + n) * LSEQ) * 256 + di;

    if (ap) {
        #pragma unroll 4
        for (int t = 0; t < LSEQ; t++) {
            const float4* ds4 = (const float4*)(dsm + t * 44);
            const float4 d0 = ds4[0], d1 = ds4[1];
            float xl = dtb;
            xl = fmaf(d0.x, dtw[0], xl); xl = fmaf(d0.y, dtw[1], xl);
            xl = fmaf(d0.z, dtw[2], xl); xl = fmaf(d0.w, dtw[3], xl);
            xl = fmaf(d1.x, dtw[4], xl); xl = fmaf(d1.y, dtw[5], xl);
            xl = fmaf(d1.z, dtw[6], xl); xl = fmaf(d1.w, dtw[7], xl);
            const float dt = (xl > 15.f) ? xl : __logf(1.f + __expf(xl));

            const float xcv = __bfloat162float(Axc[t * 264 + di]);
            const float sz  = __bfloat162float(zp[(size_t)t * 256]);
            const float du  = dt * xcv;

            const float4 B0 = ds4[2], B1 = ds4[3], B2 = ds4[4], B3 = ds4[5];
            const float4 C0 = ds4[6], C1 = ds4[7], C2 = ds4[8], C3 = ds4[9];

            const float p1 = __expf(dt * Av0);
            const float p2 = p1 * p1;
            const float p4 = p2 * p2;
            float pa = p1, pb = p2, pc = p2 * p1, pd = p4;

            h[0]  = fmaf(pa, h[0],  du * B0.x);
            h[1]  = fmaf(pb, h[1],  du * B0.y);
            h[2]  = fmaf(pc, h[2],  du * B0.z);
            h[3]  = fmaf(pd, h[3],  du * B0.w);
            pa *= p4; pb *= p4; pc *= p4; pd *= p4;
            h[4]  = fmaf(pa, h[4],  du * B1.x);
            h[5]  = fmaf(pb, h[5],  du * B1.y);
            h[6]  = fmaf(pc, h[6],  du * B1.z);
            h[7]  = fmaf(pd, h[7],  du * B1.w);
            pa *= p4; pb *= p4; pc *= p4; pd *= p4;
            h[8]  = fmaf(pa, h[8],  du * B2.x);
            h[9]  = fmaf(pb, h[9],  du * B2.y);
            h[10] = fmaf(pc, h[10], du * B2.z);
            h[11] = fmaf(pd, h[11], du * B2.w);
            pa *= p4; pb *= p4; pc *= p4; pd *= p4;
            h[12] = fmaf(pa, h[12], du * B3.x);
            h[13] = fmaf(pb, h[13], du * B3.y);
            h[14] = fmaf(pc, h[14], du * B3.z);
            h[15] = fmaf(pd, h[15], du * B3.w);

            float y0 = h[0] * C0.x;  y0 = fmaf(h[1],  C0.y, y0);
            y0 = fmaf(h[2],  C0.z, y0); y0 = fmaf(h[3],  C0.w, y0);
            float y1 = h[4] * C1.x;  y1 = fmaf(h[5],  C1.y, y1);
            y1 = fmaf(h[6],  C1.z, y1); y1 = fmaf(h[7],  C1.w, y1);
            float y2 = h[8] * C2.x;  y2 = fmaf(h[9],  C2.y, y2);
            y2 = fmaf(h[10], C2.z, y2); y2 = fmaf(h[11], C2.w, y2);
            float y3 = h[12] * C3.x; y3 = fmaf(h[13], C3.y, y3);
            y3 = fmaf(h[14], C3.z, y3); y3 = fmaf(h[15], C3.w, y3);
            const float y = (y0 + y1) + (y2 + y3);

            yp[(size_t)t * 256] = __float2bfloat16(fmaf(Dpv, xcv, y) * sz);
        }
    } else {
        for (int t = 0; t < LSEQ; t++) {
            const float* row = dsm + t * 44;
            float xl = dtb;
            #pragma unroll
            for (int k = 0; k < 8; k++) xl = fmaf(row[k], dtw[k], xl);
            const float dt = (xl > 15.f) ? xl : log1pf(__expf(xl));
            const float xcv = __bfloat162float(Axc[t * 264 + di]);
            const float sz  = __bfloat162float(zp[(size_t)t * 256]);
            const float du  = dt * xcv;
            float y = 0.f;
            #pragma unroll
            for (int s = 0; s < 16; s++) {
                const float Avs = -__expf(A_log[(r * 256 + di) * 16 + s]);
                const float dA = __expf(dt * Avs);
                h[s] = fmaf(dA, h[s], du * row[8 + s]);
                y = fmaf(h[s], row[24 + s], y);
            }
            yp[(size_t)t * 256] = __float2bfloat16(fmaf(Dpv, xcv, y) * sz);
        }
    }
}

// ---------------- launch: 3-stream branch pipeline (capture-safe fork/join) ----------------
extern "C" void kernel_launch(void* const* d_in, const int* in_sizes, int n_in,
                              void* d_out, int out_size)
{
    const float* x      = (const float*)d_in[0];
    const float* ng     = (const float*)d_in[1];
    const float* nb     = (const float*)d_in[2];
    const float* in_w   = (const float*)d_in[3];
    const float* conv_w = (const float*)d_in[4];
    const float* conv_b = (const float*)d_in[5];
    const float* xp_w   = (const float*)d_in[6];
    const float* dt_w   = (const float*)d_in[7];
    const float* dt_b   = (const float*)d_in[8];
    const float* A_log  = (const float*)d_in[9];
    const float* Dparam = (const float*)d_in[10];
    const float* out_w  = (const float*)d_in[11];
    const float* fw     = (const float*)d_in[12];
    const float* fb     = (const float*)d_in[13];
    const float* pw     = (const float*)d_in[14];
    const float* pb     = (const float*)d_in[15];
    float* out = (float*)d_out;

    static cudaStream_t s1 = nullptr, s2 = nullptr;
    static cudaEvent_t evFork, evCvt, evLn, evWc, evR1, evR2;
    if (s1 == nullptr) {
        cudaStreamCreateWithFlags(&s1, cudaStreamNonBlocking);
        cudaStreamCreateWithFlags(&s2, cudaStreamNonBlocking);
        cudaEventCreateWithFlags(&evFork, cudaEventDisableTiming);
        cudaEventCreateWithFlags(&evCvt,  cudaEventDisableTiming);
        cudaEventCreateWithFlags(&evLn,   cudaEventDisableTiming);
        cudaEventCreateWithFlags(&evWc,   cudaEventDisableTiming);
        cudaEventCreateWithFlags(&evR1,   cudaEventDisableTiming);
        cudaEventCreateWithFlags(&evR2,   cudaEventDisableTiming);
    }

    cudaEventRecord(evFork, 0);
    cudaStreamWaitEvent(s1, evFork, 0);
    cudaStreamWaitEvent(s2, evFork, 0);

    cvt_kernel<<<(3 * 512 * 128 + 255) / 256, 256, 0, s1>>>(in_w, xp_w, pw);
    cudaEventRecord(evCvt, s1);
    wcomb_kernel<<<dim3(128, 3), 256, 0, s2>>>(fw, out_w);
    cudaEventRecord(evWc, s2);
    ln_kernel<<<VV / 32, 256>>>(x, ng, nb);
    cudaEventRecord(evLn, 0);

    cudaStreamWaitEvent(0,  evCvt, 0);
    cudaStreamWaitEvent(0,  evWc,  0);
    cudaStreamWaitEvent(s1, evLn,  0);
    cudaStreamWaitEvent(s1, evWc,  0);
    cudaStreamWaitEvent(s2, evCvt, 0);
    cudaStreamWaitEvent(s2, evLn,  0);

    cudaStream_t bs[3] = { (cudaStream_t)0, s1, s2 };
    for (int r = 0; r < 3; r++) {
        cudaStream_t s = bs[r];
        bgemm128_kernel<1><<<dim3(4, VV / 128), 256, 0, s>>>(r, conv_w, conv_b);  // in_proj+conv+silu
        xscan_kernel<<<dim3(NSEQ), 256, 0, s>>>(r, dt_w, dt_b, A_log, Dparam);    // x_proj+scan fused
        bgemm128_kernel<2><<<dim3(1, VV / 128), 256, 0, s>>>(r, nullptr, nullptr); // out_proj x W'
    }
    cudaEventRecord(evR1, s1);
    cudaEventRecord(evR2, s2);

    cudaStreamWaitEvent(0, evR1, 0);
    cudaStreamWaitEvent(0, evR2, 0);
    sumgelu_kernel<<<VV * 128 / (256 * 8), 256>>>(fb);
    proj_kernel<<<dim3(VV / 64, 1), 256>>>(pb, x, out);
}